// round 9
// baseline (speedup 1.0000x reference)
#include <cuda_runtime.h>

#define B_   32
#define IN_  2048
#define DK   8      // Din
#define N_   64     // num output capsules
#define C_   32     // weight channels
#define DD   16     // Dout
#define IPC  (IN_/C_)   // 64 input capsules per channel
#define GRID 1024
#define TPB  128

// scratch (device globals — no allocation allowed)
__device__ float g_X[B_*C_*DK];        // per-channel x sums (iter 0)
__device__ float g_U[B_*N_*C_*DK];     // accumulated out^T W  (logits via U.x)
__device__ float g_y[B_*N_*C_*DK];     // coef-weighted x sums

// ---------------------------------------------------------------------------
// Hierarchical grid barrier: 32 leaf counters (padded 256B apart -> distinct
// L2 slices, 32 arrivals each) + 1 root (32 arrivals). Counters are monotonic
// (compared mod 32) -> no resets, deterministic across graph replays.
// ---------------------------------------------------------------------------
__device__ unsigned g_leaf[32*64];
__device__ unsigned g_root;
__device__ volatile unsigned g_gen;

__device__ __forceinline__ void grid_sync() {
    __syncthreads();
    if (threadIdx.x == 0) {
        unsigned gen = g_gen;
        __threadfence();                 // publish this CTA's writes
        unsigned p = atomicAdd(&g_leaf[(blockIdx.x & 31) * 64], 1u);
        if ((p & 31u) == 31u) {          // last in leaf -> arrive at root
            unsigned q = atomicAdd(&g_root, 1u);
            if ((q & 31u) == 31u) {
                __threadfence();
                g_gen = gen + 1u;        // release
            } else {
                while (g_gen == gen) __nanosleep(20);
            }
        } else {
            while (g_gen == gen) __nanosleep(20);
        }
    }
    __syncthreads();
}

// ---------------------------------------------------------------------------
// ks phase: CTA handles 2 (b,n) pairs; 2 warps per pair split the c-loop 16/16.
//   s[d] = sum_{c,k} W[n,c,d,k]*yv[b,n,c,k] (+scale) + bias[n,d]; out=squash(s)
//   MODE 0: yv = X (n-independent), scale 1/64, U  = out^T W (overwrite)
//   MODE 1: yv = g_y, U += out^T W
//   MODE 2: yv = g_y, write final output, skip U
// lane l: d = l>>1, k-quad = l&1. sbuf = 128-float smem for cross-warp combine.
// ---------------------------------------------------------------------------
template<int MODE>
__device__ __forceinline__ void ks_phase(const float* __restrict__ W,
                                         const float* __restrict__ bias,
                                         float* __restrict__ out,
                                         float* sbuf) {
    int t = threadIdx.x;
    int w = t >> 5, l = t & 31;
    int h  = w & 1;                       // c-half: [h*16, h*16+16)
    int pl = w >> 1;                      // pair-local index 0..1
    int P = blockIdx.x * 2 + pl;
    int b = P & (B_-1);
    int n = P >> 5;

    // ---- s partial over this warp's 16 channels
    const float4* Wc = (const float4*)(W + (size_t)n * C_ * DD * DK) + l;
    float acc = 0.f;
    if (MODE == 0) {
        const float4* yp = (const float4*)(g_X + b*C_*DK) + (l & 1);
        #pragma unroll 8
        for (int cc = 0; cc < 16; ++cc) {
            int c = h*16 + cc;
            float4 wv = Wc[c*32];
            float4 yv = yp[c*2];
            acc += wv.x*yv.x + wv.y*yv.y + wv.z*yv.z + wv.w*yv.w;
        }
        acc *= (1.f/64.f);
    } else {
        const float4* yp = (const float4*)(g_y + (size_t)((b*N_ + n)*C_)*DK) + (l & 1);
        #pragma unroll 8
        for (int cc = 0; cc < 16; ++cc) {
            int c = h*16 + cc;
            float4 wv = Wc[c*32];
            float4 yv = __ldcg(yp + c*2);
            acc += wv.x*yv.x + wv.y*yv.y + wv.z*yv.z + wv.w*yv.w;
        }
    }
    acc += __shfl_xor_sync(0xffffffffu, acc, 1);   // combine two k-quads per d

    // cross-warp combine of the two c-halves through smem
    sbuf[w*32 + l] = acc;
    __syncthreads();
    float s = acc + sbuf[(w^1)*32 + l] + bias[n*DD + (l >> 1)];

    // squash (redundant in both warps of the pair — avoids a second sync)
    float sq = s * s;
    #pragma unroll
    for (int off = 2; off < 32; off <<= 1) sq += __shfl_xor_sync(0xffffffffu, sq, off);
    float scale = sq / (1.f + sq) * rsqrtf(sq + 1e-7f);
    float o = scale * s;                  // out_d on lanes 2d, 2d+1

    if (MODE == 2) {
        if (h == 0 && (l & 1) == 0) out[(size_t)(b*N_ + n)*DD + (l>>1)] = o;
        return;
    }

    // ---- U partial: U[b,n,c,k] (+)= sum_d o_d * W[n,c,d,k] for this c-half
    int g = l >> 3;
    float o0 = __shfl_sync(0xffffffffu, o, (g     ) * 2);
    float o1 = __shfl_sync(0xffffffffu, o, (g +  4) * 2);
    float o2 = __shfl_sync(0xffffffffu, o, (g +  8) * 2);
    float o3 = __shfl_sync(0xffffffffu, o, (g + 12) * 2);

    const float* Ws = W + (size_t)n * C_ * DD * DK + l;
    float* Up = g_U + (size_t)((b*N_ + n)*C_) * DK;
    #pragma unroll 8
    for (int cc = 0; cc < 16; ++cc) {
        int c = h*16 + cc;
        const float* wc = Ws + c * DD * DK;
        float u = o0*wc[0] + o1*wc[32] + o2*wc[64] + o3*wc[96];
        u += __shfl_xor_sync(0xffffffffu, u, 8);
        u += __shfl_xor_sync(0xffffffffu, u, 16);
        if (l < 8) {
            if (MODE == 0) Up[c*DK + l] = u;
            else           Up[c*DK + l] = u + __ldcg(Up + c*DK + l);
        }
    }
}

// ---------------------------------------------------------------------------
// route phase: CTA = one (b,c) channel (grid is exactly B*C = 1024).
// U[b,:,c,:] (512 floats) staged to smem.
// S-phase: lanes own capsules; S_i = sum_n exp(U_n.x_i) with U broadcast from
//          smem; ONE shfl per 32-n half-range; invs[i] = 1/S_i.
// y-phase: lane l owns n0=l, n1=l+32; coef = exp(logit)*invs_i -> NO
//          reductions, NO divides in the inner loop.
// 4-way partial-y combine through smem, then write g_y.
// ---------------------------------------------------------------------------
__device__ __forceinline__ void route_phase(const float* __restrict__ x,
                                            float* xs, float* us, float* invs,
                                            float* ybuf, bool stage) {
    int t = threadIdx.x;
    int blk = blockIdx.x;
    int b = blk >> 5;                    // 32 channels per b
    int c = blk & 31;
    float4* xs4 = (float4*)xs;
    float4* us4 = (float4*)us;

    if (stage) {
        const float4* xg = (const float4*)(x + (size_t)(b*IN_ + c*IPC) * DK);
        xs4[t] = xg[t];                  // 128 float4 = 512 floats
    }
    // stage U[b,n,c,:] for all n: thread t -> (n = t>>1, half = t&1)
    {
        const float4* Ug = (const float4*)g_U
                         + ((size_t)(b*N_ + (t >> 1))*C_ + c)*2 + (t & 1);
        us4[t] = __ldcg(Ug);
    }
    __syncthreads();

    int w = t >> 5, l = t & 31;

    // ---- S-phase: warp w covers capsules [w*16, w*16+16); lane = (i, n-half)
    {
        int i  = w*16 + (l & 15);
        int nh = l >> 4;
        float4 xa = xs4[i*2], xb = xs4[i*2 + 1];
        float ssum = 0.f;
        #pragma unroll 8
        for (int nn = 0; nn < 32; ++nn) {
            int n = nh*32 + nn;
            float4 ua = us4[n*2], ub = us4[n*2 + 1];
            float lg = ua.x*xa.x + ua.y*xa.y + ua.z*xa.z + ua.w*xa.w
                     + ub.x*xb.x + ub.y*xb.y + ub.z*xb.z + ub.w*xb.w;
            ssum += __expf(lg);          // |logit| small: no max-sub needed
        }
        ssum += __shfl_xor_sync(0xffffffffu, ssum, 16);
        if (nh == 0) invs[i] = __frcp_rn(ssum);
    }
    __syncthreads();

    // ---- y-phase: register-resident U rows for n0=l, n1=l+32
    float4 u0a = us4[l*2],        u0b = us4[l*2 + 1];
    float4 u1a = us4[(l+32)*2],   u1b = us4[(l+32)*2 + 1];

    float y0a=0,y0b=0,y0c=0,y0d=0,y0e=0,y0f=0,y0g=0,y0h=0;
    float y1a=0,y1b=0,y1c=0,y1d=0,y1e=0,y1f=0,y1g=0,y1h=0;

    const float4* xw  = xs4 + w*32;      // warp's 16 capsules
    const float*  ivp = invs + w*16;
    #pragma unroll 8
    for (int i = 0; i < 16; ++i) {
        float4 xa = xw[i*2], xb = xw[i*2 + 1];
        float iv = ivp[i];
        float l0 = u0a.x*xa.x + u0a.y*xa.y + u0a.z*xa.z + u0a.w*xa.w
                 + u0b.x*xb.x + u0b.y*xb.y + u0b.z*xb.z + u0b.w*xb.w;
        float l1 = u1a.x*xa.x + u1a.y*xa.y + u1a.z*xa.z + u1a.w*xa.w
                 + u1b.x*xb.x + u1b.y*xb.y + u1b.z*xb.z + u1b.w*xb.w;
        float c0 = __expf(l0) * iv;
        float c1 = __expf(l1) * iv;
        y0a += c0*xa.x; y0b += c0*xa.y; y0c += c0*xa.z; y0d += c0*xa.w;
        y0e += c0*xb.x; y0f += c0*xb.y; y0g += c0*xb.z; y0h += c0*xb.w;
        y1a += c1*xa.x; y1b += c1*xa.y; y1c += c1*xa.z; y1d += c1*xa.w;
        y1e += c1*xb.x; y1f += c1*xb.y; y1g += c1*xb.z; y1h += c1*xb.w;
    }

    // per-warp partials -> smem (each warp: 64 n x 8 k = 128 float4)
    float4* yb4 = (float4*)ybuf + w * 128;
    yb4[l*2]          = make_float4(y0a,y0b,y0c,y0d);
    yb4[l*2 + 1]      = make_float4(y0e,y0f,y0g,y0h);
    yb4[(l+32)*2]     = make_float4(y1a,y1b,y1c,y1d);
    yb4[(l+32)*2 + 1] = make_float4(y1e,y1f,y1g,y1h);
    __syncthreads();

    // 4-way combine: thread t owns float4 slot t = (n = t>>1, half = t&1)
    float4* yb = (float4*)ybuf;
    float4 p0 = yb[t], p1 = yb[t+128], p2 = yb[t+256], p3 = yb[t+384];
    float4 r = make_float4(p0.x+p1.x+p2.x+p3.x, p0.y+p1.y+p2.y+p3.y,
                           p0.z+p1.z+p2.z+p3.z, p0.w+p1.w+p2.w+p3.w);
    int n = t >> 1, hf = t & 1;
    ((float4*)g_y)[(size_t)((b*N_ + n)*C_ + c)*2 + hf] = r;
}

// ---------------------------------------------------------------------------
// One fused persistent kernel: grid 1024 x 128, single wave guaranteed by
// __launch_bounds__(128, 8): regs<=64 -> 8 CTAs/SM -> capacity 1184 >= 1024.
// smem ~12.5KB/CTA -> 100KB/SM at 8 CTAs (228KB carveout), fine.
// ---------------------------------------------------------------------------
__global__ void __launch_bounds__(TPB, 8) fused_kernel(
        const float* __restrict__ x, const float* __restrict__ W,
        const float* __restrict__ bias, float* __restrict__ out) {
    __shared__ float xs[IPC*DK];        // 2KB: channel x tile (staged once)
    __shared__ float us[N_*DK];         // 2KB: U[b,:,c,:] tile (restaged per route)
    __shared__ float invs[IPC];         // 256B: per-capsule 1/softmax-denominator
    __shared__ float ybuf[4*N_*DK];     // 8KB: 4-warp partial-y combine / ks sbuf

    // Phase 1: X[b,c,k] = sum_{j<64} x[b, c*64+j, k]  (8192 outputs, CTAs 0..63)
    if (blockIdx.x < 64) {
        int gt = blockIdx.x * TPB + threadIdx.x;
        int b = gt >> 8;                // C_*DK = 256 per b
        int ck = gt & 255;
        const float* xp = x + (size_t)b*IN_*DK + (ck >> 3)*IPC*DK + (ck & 7);
        float s = 0.f;
        #pragma unroll 16
        for (int j = 0; j < IPC; ++j) s += xp[j*DK];
        g_X[gt] = s;
    }
    grid_sync();
    ks_phase<0>(W, bias, out, ybuf);        // iter 0: uniform coef, build U
    grid_sync();
    route_phase(x, xs, us, invs, ybuf, true);   // iter 1: softmax(U.x) -> y
    grid_sync();
    ks_phase<1>(W, bias, out, ybuf);        // iter 1: s,out, U += ...
    grid_sync();
    route_phase(x, xs, us, invs, ybuf, false);  // iter 2 (x tile already in smem)
    grid_sync();
    ks_phase<2>(W, bias, out, ybuf);        // iter 2: final output
}

// ---------------------------------------------------------------------------
extern "C" void kernel_launch(void* const* d_in, const int* in_sizes, int n_in,
                              void* d_out, int out_size) {
    const float* x    = (const float*)d_in[0];   // [32, 2048, 8]
    const float* W    = (const float*)d_in[1];   // [64, 32, 16, 8]
    const float* bias = (const float*)d_in[2];   // [64, 16]
    float* out = (float*)d_out;                  // [32, 64, 16]

    fused_kernel<<<GRID, TPB>>>(x, W, bias, out);
}

// round 12
// speedup vs baseline: 1.1902x; 1.1902x over previous
#include <cuda_runtime.h>

#define B_   32
#define IN_  2048
#define DK   8      // Din
#define N_   64     // num output capsules
#define C_   32     // weight channels
#define DD   16     // Dout
#define IPC  (IN_/C_)   // 64 input capsules per channel
#define GRID 1024
#define TPB  128

// scratch (device globals — no allocation allowed)
__device__ float g_X[B_*C_*DK];        // per-channel x sums (iter 0)
__device__ float g_U[B_*N_*C_*DK];     // accumulated out^T W  (logits via U.x)
__device__ float g_y[B_*N_*C_*DK];     // coef-weighted x sums

// ---------------------------------------------------------------------------
// Per-b barrier: 32 independent pipelines, 32 CTA arrivals each. Counters are
// monotonic (checked mod 32 / compared relatively) -> no resets, deterministic
// across graph replays. Padded 256B apart -> distinct L2 slices.
// ---------------------------------------------------------------------------
__device__ unsigned b_cnt[B_*64];
__device__ volatile unsigned b_gen[B_*64];

__device__ __forceinline__ void b_sync(int b) {
    __syncthreads();
    if (threadIdx.x == 0) {
        volatile unsigned* gp = &b_gen[b*64];
        unsigned gen = *gp;
        __threadfence();                     // publish this CTA's writes; order gen-read
        if ((atomicAdd(&b_cnt[b*64], 1u) & 31u) == 31u) {
            __threadfence();
            *gp = gen + 1u;                  // release this b-group
        } else {
            while (*gp == gen) __nanosleep(20);
        }
    }
    __syncthreads();
}

// ---------------------------------------------------------------------------
// ks phase: CTA handles (b, n0=2m) and (b, n1=2m+1); 2 warps per n split the
// c-loop 16/16.
//   s[d] = sum_{c,k} W[n,c,d,k]*yv[b,n,c,k] (+scale) + bias[n,d]; out=squash(s)
//   MODE 0: yv = X (n-independent), scale 1/64, U  = out^T W (overwrite)
//   MODE 1: yv = g_y, U += out^T W
//   MODE 2: yv = g_y, write final output, skip U
// lane l: d = l>>1, k-quad = l&1. sbuf = 128-float smem for cross-warp combine.
// ---------------------------------------------------------------------------
template<int MODE>
__device__ __forceinline__ void ks_phase(const float* __restrict__ W,
                                         const float* __restrict__ bias,
                                         float* __restrict__ out,
                                         float* sbuf, int b, int m) {
    int t = threadIdx.x;
    int w = t >> 5, l = t & 31;
    int h  = w & 1;                       // c-half: [h*16, h*16+16)
    int n = m*2 + (w >> 1);               // warps {0,1}->n=2m, {2,3}->n=2m+1

    // ---- s partial over this warp's 16 channels
    const float4* Wc = (const float4*)(W + (size_t)n * C_ * DD * DK) + l;
    float acc = 0.f;
    if (MODE == 0) {
        const float4* yp = (const float4*)(g_X + b*C_*DK) + (l & 1);
        #pragma unroll 8
        for (int cc = 0; cc < 16; ++cc) {
            int c = h*16 + cc;
            float4 wv = Wc[c*32];
            float4 yv = yp[c*2];
            acc += wv.x*yv.x + wv.y*yv.y + wv.z*yv.z + wv.w*yv.w;
        }
        acc *= (1.f/64.f);
    } else {
        const float4* yp = (const float4*)(g_y + (size_t)((b*N_ + n)*C_)*DK) + (l & 1);
        #pragma unroll 8
        for (int cc = 0; cc < 16; ++cc) {
            int c = h*16 + cc;
            float4 wv = Wc[c*32];
            float4 yv = __ldcg(yp + c*2);   // written by other CTAs of this b-group
            acc += wv.x*yv.x + wv.y*yv.y + wv.z*yv.z + wv.w*yv.w;
        }
    }
    acc += __shfl_xor_sync(0xffffffffu, acc, 1);   // combine two k-quads per d

    // cross-warp combine of the two c-halves through smem
    sbuf[w*32 + l] = acc;
    __syncthreads();
    float s = acc + sbuf[(w^1)*32 + l] + bias[n*DD + (l >> 1)];

    // squash (redundant in both warps of the pair — avoids a second sync)
    float sq = s * s;
    #pragma unroll
    for (int off = 2; off < 32; off <<= 1) sq += __shfl_xor_sync(0xffffffffu, sq, off);
    float scale = sq / (1.f + sq) * rsqrtf(sq + 1e-7f);
    float o = scale * s;                  // out_d on lanes 2d, 2d+1

    if (MODE == 2) {
        if (h == 0 && (l & 1) == 0) out[(size_t)(b*N_ + n)*DD + (l>>1)] = o;
        return;
    }

    // ---- U partial: U[b,n,c,k] (+)= sum_d o_d * W[n,c,d,k] for this c-half
    int g = l >> 3;
    float o0 = __shfl_sync(0xffffffffu, o, (g     ) * 2);
    float o1 = __shfl_sync(0xffffffffu, o, (g +  4) * 2);
    float o2 = __shfl_sync(0xffffffffu, o, (g +  8) * 2);
    float o3 = __shfl_sync(0xffffffffu, o, (g + 12) * 2);

    const float* Ws = W + (size_t)n * C_ * DD * DK + l;
    float* Up = g_U + (size_t)((b*N_ + n)*C_) * DK;
    #pragma unroll 8
    for (int cc = 0; cc < 16; ++cc) {
        int c = h*16 + cc;
        const float* wc = Ws + c * DD * DK;
        float u = o0*wc[0] + o1*wc[32] + o2*wc[64] + o3*wc[96];
        u += __shfl_xor_sync(0xffffffffu, u, 8);
        u += __shfl_xor_sync(0xffffffffu, u, 16);
        if (l < 8) {
            if (MODE == 0) Up[c*DK + l] = u;
            else           Up[c*DK + l] = u + __ldcg(Up + c*DK + l); // own warp wrote it (write-through)
        }
    }
}

// ---------------------------------------------------------------------------
// route phase: CTA = channel (b, c=m). 4 warps x 16 capsules each.
// lane l handles n0=l, n1=l+32: logits = U.x, softmax over 64 n (warp
// butterfly), register-resident partial y, 4-way combine through smem.
// x tile (512 floats) staged once (route1), reused (route2).
// ---------------------------------------------------------------------------
__device__ __forceinline__ void route_phase(const float* __restrict__ x,
                                            float* xs, float* ybuf,
                                            int b, int c, bool stage) {
    int t = threadIdx.x;
    float4* xs4 = (float4*)xs;

    if (stage) {
        const float4* xg = (const float4*)(x + (size_t)(b*IN_ + c*IPC) * DK);
        xs4[t] = xg[t];                  // 128 float4 = 512 floats
    }
    __syncthreads();

    int w = t >> 5, l = t & 31;

    // U rows for n0=l, n1=l+32 (written by other CTAs of this b-group -> ldcg)
    const float4* Ub = (const float4*)g_U + (size_t)((b*N_)*C_ + c) * 2;
    float4 u0a = __ldcg(Ub + (size_t)l*64),      u0b = __ldcg(Ub + (size_t)l*64 + 1);
    float4 u1a = __ldcg(Ub + (size_t)(l+32)*64), u1b = __ldcg(Ub + (size_t)(l+32)*64 + 1);

    float y0a=0,y0b=0,y0c=0,y0d=0,y0e=0,y0f=0,y0g=0,y0h=0;
    float y1a=0,y1b=0,y1c=0,y1d=0,y1e=0,y1f=0,y1g=0,y1h=0;

    const float4* xw = xs4 + w*32;       // warp's 16 capsules, 2 float4 each
    #pragma unroll 4
    for (int i = 0; i < 16; ++i) {
        float4 xa = xw[i*2], xb = xw[i*2 + 1];
        float l0 = u0a.x*xa.x + u0a.y*xa.y + u0a.z*xa.z + u0a.w*xa.w
                 + u0b.x*xb.x + u0b.y*xb.y + u0b.z*xb.z + u0b.w*xb.w;
        float l1 = u1a.x*xa.x + u1a.y*xa.y + u1a.z*xa.z + u1a.w*xa.w
                 + u1b.x*xb.x + u1b.y*xb.y + u1b.z*xb.z + u1b.w*xb.w;
        float e0 = __expf(l0), e1 = __expf(l1);   // |logit| small: no max-sub
        float ts = e0 + e1;
        #pragma unroll
        for (int off = 1; off < 32; off <<= 1) ts += __shfl_xor_sync(0xffffffffu, ts, off);
        float inv = __fdividef(1.f, ts);
        float c0 = e0 * inv, c1 = e1 * inv;
        y0a += c0*xa.x; y0b += c0*xa.y; y0c += c0*xa.z; y0d += c0*xa.w;
        y0e += c0*xb.x; y0f += c0*xb.y; y0g += c0*xb.z; y0h += c0*xb.w;
        y1a += c1*xa.x; y1b += c1*xa.y; y1c += c1*xa.z; y1d += c1*xa.w;
        y1e += c1*xb.x; y1f += c1*xb.y; y1g += c1*xb.z; y1h += c1*xb.w;
    }

    // per-warp partials -> smem (each warp: 64 n x 8 k = 128 float4)
    float4* yb4 = (float4*)ybuf + w * 128;
    yb4[l*2]          = make_float4(y0a,y0b,y0c,y0d);
    yb4[l*2 + 1]      = make_float4(y0e,y0f,y0g,y0h);
    yb4[(l+32)*2]     = make_float4(y1a,y1b,y1c,y1d);
    yb4[(l+32)*2 + 1] = make_float4(y1e,y1f,y1g,y1h);
    __syncthreads();

    // 4-way combine: thread t owns float4 slot t = (n = t>>1, half = t&1)
    float4* yb = (float4*)ybuf;
    float4 p0 = yb[t], p1 = yb[t+128], p2 = yb[t+256], p3 = yb[t+384];
    float4 r = make_float4(p0.x+p1.x+p2.x+p3.x, p0.y+p1.y+p2.y+p3.y,
                           p0.z+p1.z+p2.z+p3.z, p0.w+p1.w+p2.w+p3.w);
    int n = t >> 1, hf = t & 1;
    ((float4*)g_y)[(size_t)((b*N_ + n)*C_ + hf*0 + c)*2 + hf] = r;
}

// ---------------------------------------------------------------------------
// One fused persistent kernel: grid 1024 x 128 = 32 independent b-pipelines
// of 32 CTAs each. Single wave guaranteed by __launch_bounds__(128, 8):
// regs<=64 -> 8 CTAs/SM -> capacity 1184 >= 1024. smem 10KB/CTA.
// ---------------------------------------------------------------------------
__global__ void __launch_bounds__(TPB, 8) fused_kernel(
        const float* __restrict__ x, const float* __restrict__ W,
        const float* __restrict__ bias, float* __restrict__ out) {
    __shared__ float xs[IPC*DK];        // 2KB: channel x tile (staged once)
    __shared__ float ybuf[4*N_*DK];     // 8KB: 4-warp partial-y combine / ks sbuf

    int b = blockIdx.x >> 5;            // pipeline id (batch index)
    int m = blockIdx.x & 31;            // CTA index within pipeline

    // Phase 1: X[b,c,k] = sum_{j<64} x[b, c*64+j, k]
    // CTA m computes 8 outputs ck = m*8..m*8+7: 16 lanes/output, 4 loads/lane.
    {
        int w = threadIdx.x >> 5, l = threadIdx.x & 31;
        int ck = m*8 + w*2 + (l >> 4);
        int c = ck >> 3, k = ck & 7;
        int sub = l & 15;
        const float* xp = x + (size_t)b*IN_*DK + (size_t)c*IPC*DK + sub*4*DK + k;
        float s = xp[0] + xp[DK] + xp[2*DK] + xp[3*DK];
        s += __shfl_xor_sync(0xffffffffu, s, 1);
        s += __shfl_xor_sync(0xffffffffu, s, 2);
        s += __shfl_xor_sync(0xffffffffu, s, 4);
        s += __shfl_xor_sync(0xffffffffu, s, 8);
        if (sub == 0) g_X[b*C_*DK + ck] = s;
    }
    b_sync(b);
    ks_phase<0>(W, bias, out, ybuf, b, m);   // iter 0: uniform coef, build U
    b_sync(b);
    route_phase(x, xs, ybuf, b, m, true);    // iter 1: softmax(U.x) -> y
    b_sync(b);
    ks_phase<1>(W, bias, out, ybuf, b, m);   // iter 1: s,out, U += ...
    b_sync(b);
    route_phase(x, xs, ybuf, b, m, false);   // iter 2 (x tile already in smem)
    b_sync(b);
    ks_phase<2>(W, bias, out, ybuf, b, m);   // iter 2: final output
}

// ---------------------------------------------------------------------------
extern "C" void kernel_launch(void* const* d_in, const int* in_sizes, int n_in,
                              void* d_out, int out_size) {
    const float* x    = (const float*)d_in[0];   // [32, 2048, 8]
    const float* W    = (const float*)d_in[1];   // [64, 32, 16, 8]
    const float* bias = (const float*)d_in[2];   // [64, 16]
    float* out = (float*)d_out;                  // [32, 64, 16]

    fused_kernel<<<GRID, TPB>>>(x, W, bias, out);
}